// round 2
// baseline (speedup 1.0000x reference)
#include <cuda_runtime.h>
#include <cstdint>

#define N_NODES 50000
#define E_EDGES 1600000
#define F_IN    32
#define HEADS   8
#define D_HEAD  16
#define HID     128
#define ED      16
#define G_GRAPHS 512
#define MH      512
#define MO      512
#define SLOPE   0.2f

#define ENTRIES (E_EDGES + N_NODES)
#define FULLMASK 0xffffffffu

// ---------------- scratch (device globals; no allocation allowed) ----------------
__device__ int   g_deg[N_NODES];
__device__ int   g_cursor[N_NODES];
__device__ int   g_rowptr[N_NODES + 1];
__device__ int   g_src_sorted[E_EDGES];
__device__ int   g_dst_sorted[E_EDGES];
__device__ float g_ea_sorted[(size_t)E_EDGES * ED];
__device__ float g_loop_attr[(size_t)N_NODES * ED];
__device__ float g_s[(size_t)E_EDGES * HEADS];
__device__ float g_s_loop[(size_t)N_NODES * HEADS];
__device__ float g_xl[(size_t)N_NODES * HID];
__device__ float g_xr[(size_t)N_NODES * HID];
__device__ float g_h1[(size_t)N_NODES * HID];
__device__ float g_h2[(size_t)N_NODES * HID];
__device__ float g_pool[(size_t)G_GRAPHS * HID];

// ---------------- preprocessing ----------------
__global__ void zero_prep_kernel() {
    int i = blockIdx.x * blockDim.x + threadIdx.x;
    if (i < N_NODES) { g_deg[i] = 0; g_cursor[i] = 0; }
}

__global__ void zero_pool_kernel() {
    int i = blockIdx.x * blockDim.x + threadIdx.x;
    if (i < G_GRAPHS * HID) g_pool[i] = 0.f;
}

__global__ void hist_kernel(const int* __restrict__ dst) {
    int e = blockIdx.x * blockDim.x + threadIdx.x;
    if (e < E_EDGES) atomicAdd(&g_deg[dst[e]], 1);
}

// single-block exclusive scan of g_deg -> g_rowptr
__global__ void scan_kernel() {
    __shared__ int tmp[1024];
    __shared__ int carry_s;
    int tid = threadIdx.x;
    if (tid == 0) carry_s = 0;
    __syncthreads();
    for (int base = 0; base < N_NODES; base += 1024) {
        int i = base + tid;
        int v = (i < N_NODES) ? g_deg[i] : 0;
        tmp[tid] = v;
        __syncthreads();
        for (int off = 1; off < 1024; off <<= 1) {
            int t = (tid >= off) ? tmp[tid - off] : 0;
            __syncthreads();
            tmp[tid] += t;
            __syncthreads();
        }
        int carry = carry_s;
        if (i < N_NODES) g_rowptr[i] = carry + tmp[tid] - v;
        __syncthreads();
        if (tid == 1023) carry_s = carry + tmp[1023];
        __syncthreads();
    }
    if (tid == 0) g_rowptr[N_NODES] = carry_s;
}

__global__ __launch_bounds__(256) void scatter_kernel(const int* __restrict__ src,
                                                      const int* __restrict__ dst,
                                                      const float* __restrict__ ea) {
    int e = blockIdx.x * blockDim.x + threadIdx.x;
    if (e >= E_EDGES) return;
    int d = dst[e];
    int slot = g_rowptr[d] + atomicAdd(&g_cursor[d], 1);
    g_src_sorted[slot] = src[e];
    const float4* s4 = (const float4*)(ea + (size_t)e * ED);
    float4* d4 = (float4*)(g_ea_sorted + (size_t)slot * ED);
    d4[0] = s4[0]; d4[1] = s4[1]; d4[2] = s4[2]; d4[3] = s4[3];
}

// warp per node: fill dst_sorted (coalesced) + self-loop attr = mean of incoming edge_attr
__global__ __launch_bounds__(256) void loopattr_kernel() {
    int w = (blockIdx.x * blockDim.x + threadIdx.x) >> 5;
    int lane = threadIdx.x & 31;
    if (w >= N_NODES) return;
    int beg = g_rowptr[w], end = g_rowptr[w + 1];
    for (int p = beg + lane; p < end; p += 32) g_dst_sorted[p] = w;
    int cnt = end - beg;
    float inv = 1.f / (float)max(cnt, 1);
    if (lane < ED) {
        float s = 0.f;
        for (int p = beg; p < end; p++) s += g_ea_sorted[(size_t)p * ED + lane];
        g_loop_attr[(size_t)w * ED + lane] = s * inv;
    }
}

// ---------------- node linear transforms (xl = h Wl + bl, xr = h Wr + br) ----------------
template<int F>
__global__ __launch_bounds__(128) void lin_kernel(int sel, const float* __restrict__ x,
                           const float* __restrict__ Wl, const float* __restrict__ bl,
                           const float* __restrict__ Wr, const float* __restrict__ br) {
    const float* hin = (sel == 0) ? x : (sel == 1 ? g_h1 : g_h2);
    __shared__ float hr[4][F];
    int v0 = blockIdx.x * 4;
    int t = threadIdx.x;  // 128 threads, t = output column
    for (int i = t; i < 4 * F; i += 128) {
        int n = i / F, k = i - n * F;
        int v = v0 + n;
        hr[n][k] = (v < N_NODES) ? hin[(size_t)v * F + k] : 0.f;
    }
    __syncthreads();
    float bL = bl[t], bR = br[t];
    float al0 = bL, al1 = bL, al2 = bL, al3 = bL;
    float ar0 = bR, ar1 = bR, ar2 = bR, ar3 = bR;
#pragma unroll 8
    for (int k = 0; k < F; k++) {
        float wl = Wl[k * HID + t];
        float wr = Wr[k * HID + t];
        al0 += hr[0][k] * wl; al1 += hr[1][k] * wl; al2 += hr[2][k] * wl; al3 += hr[3][k] * wl;
        ar0 += hr[0][k] * wr; ar1 += hr[1][k] * wr; ar2 += hr[2][k] * wr; ar3 += hr[3][k] * wr;
    }
    if (v0 + 0 < N_NODES) { g_xl[(size_t)(v0 + 0) * HID + t] = al0; g_xr[(size_t)(v0 + 0) * HID + t] = ar0; }
    if (v0 + 1 < N_NODES) { g_xl[(size_t)(v0 + 1) * HID + t] = al1; g_xr[(size_t)(v0 + 1) * HID + t] = ar1; }
    if (v0 + 2 < N_NODES) { g_xl[(size_t)(v0 + 2) * HID + t] = al2; g_xr[(size_t)(v0 + 2) * HID + t] = ar2; }
    if (v0 + 3 < N_NODES) { g_xl[(size_t)(v0 + 3) * HID + t] = al3; g_xr[(size_t)(v0 + 3) * HID + t] = ar3; }
}

// ---------------- per-edge attention logits (warp per edge entry) ----------------
__global__ __launch_bounds__(256) void scores_kernel(const float* __restrict__ We,
                                                     const float* __restrict__ att) {
    int w = (blockIdx.x * blockDim.x + threadIdx.x) >> 5;
    int lane = threadIdx.x & 31;
    if (w >= ENTRIES) return;
    const float* ea_ptr;
    const float* xl_row;
    const float* xr_row;
    float* s_out;
    if (w < E_EDGES) {
        int s = g_src_sorted[w];
        int d = g_dst_sorted[w];
        ea_ptr = g_ea_sorted + (size_t)w * ED;
        xl_row = g_xl + (size_t)s * HID;
        xr_row = g_xr + (size_t)d * HID;
        s_out  = g_s + (size_t)w * HEADS;
    } else {
        int v = w - E_EDGES;
        ea_ptr = g_loop_attr + (size_t)v * ED;
        xl_row = g_xl + (size_t)v * HID;
        xr_row = g_xr + (size_t)v * HID;
        s_out  = g_s_loop + (size_t)v * HEADS;
    }
    float eav = (lane < ED) ? ea_ptr[lane] : 0.f;
    float4 xl4 = ((const float4*)xl_row)[lane];
    float4 xr4 = ((const float4*)xr_row)[lane];
    float4 ee = make_float4(0.f, 0.f, 0.f, 0.f);
#pragma unroll
    for (int k = 0; k < ED; k++) {
        float a = __shfl_sync(FULLMASK, eav, k);
        float4 wv = ((const float4*)We)[k * 32 + lane];
        ee.x += a * wv.x; ee.y += a * wv.y; ee.z += a * wv.z; ee.w += a * wv.w;
    }
    float4 m;
    m.x = xl4.x + xr4.x + ee.x; m.x = (m.x > 0.f) ? m.x : SLOPE * m.x;
    m.y = xl4.y + xr4.y + ee.y; m.y = (m.y > 0.f) ? m.y : SLOPE * m.y;
    m.z = xl4.z + xr4.z + ee.z; m.z = (m.z > 0.f) ? m.z : SLOPE * m.z;
    m.w = xl4.w + xr4.w + ee.w; m.w = (m.w > 0.f) ? m.w : SLOPE * m.w;
    float4 a4 = ((const float4*)att)[lane];
    float sp = m.x * a4.x + m.y * a4.y + m.z * a4.z + m.w * a4.w;
    sp += __shfl_xor_sync(FULLMASK, sp, 1);
    sp += __shfl_xor_sync(FULLMASK, sp, 2);
    if ((lane & 3) == 0) s_out[lane >> 2] = sp;
}

// ---------------- softmax + aggregation (warp per node) ----------------
__global__ __launch_bounds__(256) void aggregate_kernel(const float* __restrict__ bias,
                                                        int outsel, int do_relu) {
    int v = (blockIdx.x * blockDim.x + threadIdx.x) >> 5;
    int lane = threadIdx.x & 31;
    if (v >= N_NODES) return;
    float* hout = (outsel == 1) ? g_h1 : g_h2;
    int beg = g_rowptr[v], end = g_rowptr[v + 1];
    const float* sseg = g_s + (size_t)beg * HEADS;
    int total = (end - beg) * HEADS;
    int h = lane & 7;
    float sl = g_s_loop[(size_t)v * HEADS + h];
    // max per head (lane i handles score elements with index % 8 == i % 8)
    float mx = sl;
    for (int i = lane; i < total; i += 32) mx = fmaxf(mx, sseg[i]);
    mx = fmaxf(mx, __shfl_xor_sync(FULLMASK, mx, 8));
    mx = fmaxf(mx, __shfl_xor_sync(FULLMASK, mx, 16));
    // denominator
    float dp = 0.f;
    for (int i = lane; i < total; i += 32) dp += __expf(sseg[i] - mx);
    dp += __shfl_xor_sync(FULLMASK, dp, 8);
    dp += __shfl_xor_sync(FULLMASK, dp, 16);
    dp += __expf(sl - mx);
    float rden = 1.f / dp;
    // aggregation: lane owns cols {lane, lane+32, lane+64, lane+96}
    float acc0 = 0.f, acc1 = 0.f, acc2 = 0.f, acc3 = 0.f;
    int hi = lane >> 4;
    for (int p = beg; p < end; p++) {
        int s = g_src_sorted[p];
        float exl = (lane < 8) ? __expf(g_s[(size_t)p * HEADS + lane] - mx) * rden : 0.f;
        const float* xls = g_xl + (size_t)s * HID;
        float a0 = __shfl_sync(FULLMASK, exl, 0 + hi);
        float a1 = __shfl_sync(FULLMASK, exl, 2 + hi);
        float a2 = __shfl_sync(FULLMASK, exl, 4 + hi);
        float a3 = __shfl_sync(FULLMASK, exl, 6 + hi);
        acc0 += a0 * xls[lane];
        acc1 += a1 * xls[lane + 32];
        acc2 += a2 * xls[lane + 64];
        acc3 += a3 * xls[lane + 96];
    }
    { // self-loop: sl already holds this node's head logits on lanes 0..7
        float exl = (lane < 8) ? __expf(sl - mx) * rden : 0.f;
        const float* xls = g_xl + (size_t)v * HID;
        float a0 = __shfl_sync(FULLMASK, exl, 0 + hi);
        float a1 = __shfl_sync(FULLMASK, exl, 2 + hi);
        float a2 = __shfl_sync(FULLMASK, exl, 4 + hi);
        float a3 = __shfl_sync(FULLMASK, exl, 6 + hi);
        acc0 += a0 * xls[lane];
        acc1 += a1 * xls[lane + 32];
        acc2 += a2 * xls[lane + 64];
        acc3 += a3 * xls[lane + 96];
    }
    float o;
    o = acc0 + bias[lane];      if (do_relu) o = fmaxf(o, 0.f); hout[(size_t)v * HID + lane]      = o;
    o = acc1 + bias[lane + 32]; if (do_relu) o = fmaxf(o, 0.f); hout[(size_t)v * HID + lane + 32] = o;
    o = acc2 + bias[lane + 64]; if (do_relu) o = fmaxf(o, 0.f); hout[(size_t)v * HID + lane + 64] = o;
    o = acc3 + bias[lane + 96]; if (do_relu) o = fmaxf(o, 0.f); hout[(size_t)v * HID + lane + 96] = o;
}

// ---------------- pooling ----------------
__global__ __launch_bounds__(256) void pool_kernel(const int* __restrict__ batch, int insel) {
    const float* hin = (insel == 1) ? g_h1 : g_h2;
    int idx = blockIdx.x * blockDim.x + threadIdx.x;
    if (idx >= N_NODES * HID) return;
    int v = idx >> 7;
    int c = idx & 127;
    atomicAdd(&g_pool[(size_t)batch[v] * HID + c], hin[idx]);
}

// ---------------- MLP head: relu(g W1 + b1) -> LayerNorm -> W2 + b2 ----------------
__global__ __launch_bounds__(512) void mlp_kernel(const float* __restrict__ mW1, const float* __restrict__ mb1,
                           const float* __restrict__ lng, const float* __restrict__ lnb,
                           const float* __restrict__ mW2, const float* __restrict__ mb2,
                           float* __restrict__ out) {
    int b = blockIdx.x;
    int t = threadIdx.x;  // 512 threads
    __shared__ float gr[HID];
    __shared__ float z[MH];
    __shared__ float red1[16], red2[16];
    __shared__ float s_mu, s_rstd;
    if (t < HID) gr[t] = g_pool[(size_t)b * HID + t];
    __syncthreads();
    float acc = mb1[t];
#pragma unroll 16
    for (int k = 0; k < HID; k++) acc += gr[k] * mW1[k * MH + t];
    acc = fmaxf(acc, 0.f);
    float s1 = acc, s2 = acc * acc;
#pragma unroll
    for (int off = 16; off; off >>= 1) {
        s1 += __shfl_xor_sync(FULLMASK, s1, off);
        s2 += __shfl_xor_sync(FULLMASK, s2, off);
    }
    int w = t >> 5, lane = t & 31;
    if (lane == 0) { red1[w] = s1; red2[w] = s2; }
    __syncthreads();
    if (t == 0) {
        float a = 0.f, c = 0.f;
#pragma unroll
        for (int i = 0; i < 16; i++) { a += red1[i]; c += red2[i]; }
        float mu = a / (float)MH;
        float var = c / (float)MH - mu * mu;
        s_mu = mu;
        s_rstd = rsqrtf(var + 1e-5f);
    }
    __syncthreads();
    z[t] = (acc - s_mu) * s_rstd * lng[t] + lnb[t];
    __syncthreads();
    float o = mb2[t];
#pragma unroll 8
    for (int k = 0; k < MH; k++) o += z[k] * mW2[k * MO + t];
    out[(size_t)b * MO + t] = o;
}

// ---------------- launch ----------------
extern "C" void kernel_launch(void* const* d_in, const int* in_sizes, int n_in,
                              void* d_out, int out_size) {
    const float* x   = (const float*)d_in[0];
    const int*   ei  = (const int*)d_in[1];
    const int*   src = ei;
    const int*   dst = ei + E_EDGES;
    const float* ea  = (const float*)d_in[2];
    const int*   batch = (const int*)d_in[3];
    float* out = (float*)d_out;

    const float* Wl[3]  = { (const float*)d_in[4],  (const float*)d_in[11], (const float*)d_in[18] };
    const float* bl[3]  = { (const float*)d_in[5],  (const float*)d_in[12], (const float*)d_in[19] };
    const float* Wr[3]  = { (const float*)d_in[6],  (const float*)d_in[13], (const float*)d_in[20] };
    const float* br[3]  = { (const float*)d_in[7],  (const float*)d_in[14], (const float*)d_in[21] };
    const float* We[3]  = { (const float*)d_in[8],  (const float*)d_in[15], (const float*)d_in[22] };
    const float* att[3] = { (const float*)d_in[9],  (const float*)d_in[16], (const float*)d_in[23] };
    const float* bo[3]  = { (const float*)d_in[10], (const float*)d_in[17], (const float*)d_in[24] };
    const float* mW1 = (const float*)d_in[25];
    const float* mb1 = (const float*)d_in[26];
    const float* lng = (const float*)d_in[27];
    const float* lnb = (const float*)d_in[28];
    const float* mW2 = (const float*)d_in[29];
    const float* mb2 = (const float*)d_in[30];

    const int TB = 256;
    // preprocessing: CSR by dst + sorted edge attrs + self-loop attrs
    zero_prep_kernel<<<(N_NODES + TB - 1) / TB, TB>>>();
    hist_kernel<<<(E_EDGES + TB - 1) / TB, TB>>>(dst);
    scan_kernel<<<1, 1024>>>();
    scatter_kernel<<<(E_EDGES + TB - 1) / TB, TB>>>(src, dst, ea);
    loopattr_kernel<<<(N_NODES * 32 + TB - 1) / TB, TB>>>();

    const int lin_blocks = (N_NODES + 3) / 4;
    const long long score_threads = (long long)ENTRIES * 32;
    const int score_blocks = (int)((score_threads + TB - 1) / TB);
    const int agg_blocks = (N_NODES * 32 + TB - 1) / TB;

    // layer 0: x -> g_h1
    lin_kernel<F_IN><<<lin_blocks, 128>>>(0, x, Wl[0], bl[0], Wr[0], br[0]);
    scores_kernel<<<score_blocks, TB>>>(We[0], att[0]);
    aggregate_kernel<<<agg_blocks, TB>>>(bo[0], /*outsel=*/1, /*relu=*/1);
    // layer 1: g_h1 -> g_h2
    lin_kernel<HID><<<lin_blocks, 128>>>(1, x, Wl[1], bl[1], Wr[1], br[1]);
    scores_kernel<<<score_blocks, TB>>>(We[1], att[1]);
    aggregate_kernel<<<agg_blocks, TB>>>(bo[1], /*outsel=*/2, /*relu=*/1);
    // layer 2: g_h2 -> g_h1
    lin_kernel<HID><<<lin_blocks, 128>>>(2, x, Wl[2], bl[2], Wr[2], br[2]);
    scores_kernel<<<score_blocks, TB>>>(We[2], att[2]);
    aggregate_kernel<<<agg_blocks, TB>>>(bo[2], /*outsel=*/1, /*relu=*/0);

    // pooling + MLP head
    zero_pool_kernel<<<(G_GRAPHS * HID + TB - 1) / TB, TB>>>();
    pool_kernel<<<(N_NODES * HID + TB - 1) / TB, TB>>>(batch, /*insel=*/1);
    mlp_kernel<<<G_GRAPHS, MH>>>(mW1, mb1, lng, lnb, mW2, mb2, out);
}

// round 5
// speedup vs baseline: 1.2372x; 1.2372x over previous
#include <cuda_runtime.h>
#include <cstdint>

#define N_NODES 50000
#define E_EDGES 1600000
#define F_IN    32
#define HEADS   8
#define D_HEAD  16
#define HID     128
#define ED      16
#define G_GRAPHS 512
#define MH      512
#define MO      512
#define SLOPE   0.2f

#define FULLMASK 0xffffffffu

// ---------------- scratch (device globals; no allocation allowed) ----------------
__device__ int   g_deg[N_NODES];
__device__ int   g_cursor[N_NODES];
__device__ int   g_rowptr[N_NODES + 1];
__device__ int   g_bsum[64];
__device__ int   g_src_sorted[E_EDGES];
__device__ float g_ea_sorted[(size_t)E_EDGES * ED];
__device__ float g_loop_attr[(size_t)N_NODES * ED];
__device__ float g_xl[(size_t)N_NODES * HID];
__device__ float g_xr[(size_t)N_NODES * HID];
__device__ float g_h1[(size_t)N_NODES * HID];
__device__ float g_h2[(size_t)N_NODES * HID];
__device__ float g_pool[(size_t)G_GRAPHS * HID];

// ---------------- preprocessing ----------------
__global__ void zero_prep_kernel() {
    int i = blockIdx.x * blockDim.x + threadIdx.x;
    if (i < N_NODES) { g_deg[i] = 0; g_cursor[i] = 0; }
}

__global__ void zero_pool_kernel() {
    int i = blockIdx.x * blockDim.x + threadIdx.x;
    if (i < G_GRAPHS * HID) g_pool[i] = 0.f;
}

__global__ void hist_kernel(const int* __restrict__ dst) {
    int e = blockIdx.x * blockDim.x + threadIdx.x;
    if (e < E_EDGES) atomicAdd(&g_deg[dst[e]], 1);
}

// ---- 3-phase scan: local tile scan -> scan of block sums -> add offsets ----
#define SCAN_BLOCKS ((N_NODES + 1023) / 1024)

__global__ __launch_bounds__(1024) void scan1_kernel() {
    __shared__ int tmp[1024];
    int tid = threadIdx.x;
    int i = blockIdx.x * 1024 + tid;
    int v = (i < N_NODES) ? g_deg[i] : 0;
    tmp[tid] = v;
    __syncthreads();
#pragma unroll
    for (int off = 1; off < 1024; off <<= 1) {
        int t = (tid >= off) ? tmp[tid - off] : 0;
        __syncthreads();
        tmp[tid] += t;
        __syncthreads();
    }
    if (i < N_NODES) g_rowptr[i] = tmp[tid] - v;   // local exclusive
    if (tid == 1023) g_bsum[blockIdx.x] = tmp[1023];
}

__global__ __launch_bounds__(64) void scan2_kernel() {
    __shared__ int tmp[64];
    int t = threadIdx.x;
    int v = (t < SCAN_BLOCKS) ? g_bsum[t] : 0;
    tmp[t] = v;
    __syncthreads();
#pragma unroll
    for (int off = 1; off < 64; off <<= 1) {
        int a = (t >= off) ? tmp[t - off] : 0;
        __syncthreads();
        tmp[t] += a;
        __syncthreads();
    }
    if (t < SCAN_BLOCKS) g_bsum[t] = tmp[t] - v;   // exclusive block offsets
    if (t == 0) g_rowptr[N_NODES] = E_EDGES;
}

__global__ __launch_bounds__(1024) void scan3_kernel() {
    int i = blockIdx.x * 1024 + threadIdx.x;
    if (i < N_NODES) g_rowptr[i] += g_bsum[blockIdx.x];
}

__global__ __launch_bounds__(256) void scatter_kernel(const int* __restrict__ src,
                                                      const int* __restrict__ dst,
                                                      const float* __restrict__ ea) {
    int e = blockIdx.x * blockDim.x + threadIdx.x;
    if (e >= E_EDGES) return;
    int d = dst[e];
    int slot = g_rowptr[d] + atomicAdd(&g_cursor[d], 1);
    g_src_sorted[slot] = src[e];
    const float4* s4 = (const float4*)(ea + (size_t)e * ED);
    float4* d4 = (float4*)(g_ea_sorted + (size_t)slot * ED);
    d4[0] = s4[0]; d4[1] = s4[1]; d4[2] = s4[2]; d4[3] = s4[3];
}

// warp per node: self-loop attr = mean of incoming edge_attr
__global__ __launch_bounds__(256) void loopattr_kernel() {
    int w = (blockIdx.x * blockDim.x + threadIdx.x) >> 5;
    int lane = threadIdx.x & 31;
    if (w >= N_NODES) return;
    int beg = g_rowptr[w], end = g_rowptr[w + 1];
    int cnt = end - beg;
    float inv = 1.f / (float)max(cnt, 1);
    if (lane < ED) {
        float s = 0.f;
        for (int p = beg; p < end; p++) s += g_ea_sorted[(size_t)p * ED + lane];
        g_loop_attr[(size_t)w * ED + lane] = s * inv;
    }
}

// ---------------- node linear transforms (xl = h Wl + bl, xr = h Wr + br) ----------------
template<int F>
__global__ __launch_bounds__(128) void lin_kernel(int sel, const float* __restrict__ x,
                           const float* __restrict__ Wl, const float* __restrict__ bl,
                           const float* __restrict__ Wr, const float* __restrict__ br) {
    const float* hin = (sel == 0) ? x : (sel == 1 ? g_h1 : g_h2);
    __shared__ float hr[8][F];
    int v0 = blockIdx.x * 8;
    int t = threadIdx.x;  // 128 threads, t = output column
    for (int i = t; i < 8 * F; i += 128) {
        int n = i / F, k = i - n * F;
        int v = v0 + n;
        hr[n][k] = (v < N_NODES) ? hin[(size_t)v * F + k] : 0.f;
    }
    __syncthreads();
    float bL = bl[t], bR = br[t];
    float al[8], ar[8];
#pragma unroll
    for (int n = 0; n < 8; n++) { al[n] = bL; ar[n] = bR; }
#pragma unroll 4
    for (int k = 0; k < F; k++) {
        float wl = Wl[k * HID + t];
        float wr = Wr[k * HID + t];
#pragma unroll
        for (int n = 0; n < 8; n++) {
            al[n] += hr[n][k] * wl;
            ar[n] += hr[n][k] * wr;
        }
    }
#pragma unroll
    for (int n = 0; n < 8; n++) {
        int v = v0 + n;
        if (v < N_NODES) {
            g_xl[(size_t)v * HID + t] = al[n];
            g_xr[(size_t)v * HID + t] = ar[n];
        }
    }
}

// ---------------- fused scores + online-softmax + aggregation (warp per node) ----------------
// Lane owns 4 consecutive columns [4*lane, 4*lane+3], all within head (lane/4).
// We kept in registers (16 x float4 per lane). Softmax state per lane is scalar
// (mx, den) since all 4 owned columns share one head.
__global__ __launch_bounds__(256) void fused_gat_kernel(
    const float* __restrict__ We, const float* __restrict__ att,
    const float* __restrict__ bias, int outsel, int do_relu) {
    int v = (blockIdx.x * blockDim.x + threadIdx.x) >> 5;
    int lane = threadIdx.x & 31;
    if (v >= N_NODES) return;
    float* hout = (outsel == 1) ? g_h1 : g_h2;

    // one-time per-warp loads
    float4 w[ED];
#pragma unroll
    for (int k = 0; k < ED; k++) w[k] = ((const float4*)We)[k * 32 + lane];
    float4 att4 = ((const float4*)att)[lane];
    float4 xr4 = ((const float4*)g_xr)[(size_t)v * 32 + lane];

    int beg = g_rowptr[v], end = g_rowptr[v + 1];

    // ---- self-loop first (initializes softmax state) ----
    float eav = (lane < ED) ? g_loop_attr[(size_t)v * ED + lane] : 0.f;
    float4 xls = ((const float4*)g_xl)[(size_t)v * 32 + lane];
    float4 ee = make_float4(0.f, 0.f, 0.f, 0.f);
#pragma unroll
    for (int k = 0; k < ED; k++) {
        float a = __shfl_sync(FULLMASK, eav, k);
        ee.x += a * w[k].x; ee.y += a * w[k].y; ee.z += a * w[k].z; ee.w += a * w[k].w;
    }
    float m0 = xls.x + xr4.x + ee.x; m0 = fmaxf(m0, SLOPE * m0);
    float m1 = xls.y + xr4.y + ee.y; m1 = fmaxf(m1, SLOPE * m1);
    float m2 = xls.z + xr4.z + ee.z; m2 = fmaxf(m2, SLOPE * m2);
    float m3 = xls.w + xr4.w + ee.w; m3 = fmaxf(m3, SLOPE * m3);
    float p = m0 * att4.x + m1 * att4.y + m2 * att4.z + m3 * att4.w;
    p += __shfl_xor_sync(FULLMASK, p, 1);
    p += __shfl_xor_sync(FULLMASK, p, 2);   // s for this lane's head
    float mx = p;
    float den = 1.f;
    float4 acc = xls;

    // ---- incoming edges (prefetch next src/ea to break load->use chain) ----
    int   s_next  = (beg < end) ? g_src_sorted[beg] : 0;
    float ea_next = (beg < end && lane < ED) ? g_ea_sorted[(size_t)beg * ED + lane] : 0.f;
    for (int e = beg; e < end; e++) {
        int s = s_next;
        eav = ea_next;
        if (e + 1 < end) {
            s_next  = g_src_sorted[e + 1];
            ea_next = (lane < ED) ? g_ea_sorted[(size_t)(e + 1) * ED + lane] : 0.f;
        }
        xls = ((const float4*)g_xl)[(size_t)s * 32 + lane];
        ee = make_float4(0.f, 0.f, 0.f, 0.f);
#pragma unroll
        for (int k = 0; k < ED; k++) {
            float a = __shfl_sync(FULLMASK, eav, k);
            ee.x += a * w[k].x; ee.y += a * w[k].y; ee.z += a * w[k].z; ee.w += a * w[k].w;
        }
        m0 = xls.x + xr4.x + ee.x; m0 = fmaxf(m0, SLOPE * m0);
        m1 = xls.y + xr4.y + ee.y; m1 = fmaxf(m1, SLOPE * m1);
        m2 = xls.z + xr4.z + ee.z; m2 = fmaxf(m2, SLOPE * m2);
        m3 = xls.w + xr4.w + ee.w; m3 = fmaxf(m3, SLOPE * m3);
        p = m0 * att4.x + m1 * att4.y + m2 * att4.z + m3 * att4.w;
        p += __shfl_xor_sync(FULLMASK, p, 1);
        p += __shfl_xor_sync(FULLMASK, p, 2);
        if (p <= mx) {
            float f = __expf(p - mx);
            den += f;
            acc.x += f * xls.x; acc.y += f * xls.y; acc.z += f * xls.z; acc.w += f * xls.w;
        } else {
            float sc = __expf(mx - p);
            den = den * sc + 1.f;
            acc.x = acc.x * sc + xls.x; acc.y = acc.y * sc + xls.y;
            acc.z = acc.z * sc + xls.z; acc.w = acc.w * sc + xls.w;
            mx = p;
        }
    }

    float inv = 1.f / den;
    float4 b4 = ((const float4*)bias)[lane];
    float4 o;
    o.x = acc.x * inv + b4.x; o.y = acc.y * inv + b4.y;
    o.z = acc.z * inv + b4.z; o.w = acc.w * inv + b4.w;
    if (do_relu) {
        o.x = fmaxf(o.x, 0.f); o.y = fmaxf(o.y, 0.f);
        o.z = fmaxf(o.z, 0.f); o.w = fmaxf(o.w, 0.f);
    }
    ((float4*)hout)[(size_t)v * 32 + lane] = o;
}

// ---------------- pooling ----------------
__global__ __launch_bounds__(256) void pool_kernel(const int* __restrict__ batch, int insel) {
    const float* hin = (insel == 1) ? g_h1 : g_h2;
    int idx = blockIdx.x * blockDim.x + threadIdx.x;
    if (idx >= N_NODES * HID) return;
    int v = idx >> 7;
    int c = idx & 127;
    atomicAdd(&g_pool[(size_t)batch[v] * HID + c], hin[idx]);
}

// ---------------- MLP head: relu(g W1 + b1) -> LayerNorm -> W2 + b2 ----------------
__global__ __launch_bounds__(512) void mlp_kernel(const float* __restrict__ mW1, const float* __restrict__ mb1,
                           const float* __restrict__ lng, const float* __restrict__ lnb,
                           const float* __restrict__ mW2, const float* __restrict__ mb2,
                           float* __restrict__ out) {
    int b = blockIdx.x;
    int t = threadIdx.x;  // 512 threads
    __shared__ float gr[HID];
    __shared__ float z[MH];
    __shared__ float red1[16], red2[16];
    __shared__ float s_mu, s_rstd;
    if (t < HID) gr[t] = g_pool[(size_t)b * HID + t];
    __syncthreads();
    float acc = mb1[t];
#pragma unroll 16
    for (int k = 0; k < HID; k++) acc += gr[k] * mW1[k * MH + t];
    acc = fmaxf(acc, 0.f);
    float s1 = acc, s2 = acc * acc;
#pragma unroll
    for (int off = 16; off; off >>= 1) {
        s1 += __shfl_xor_sync(FULLMASK, s1, off);
        s2 += __shfl_xor_sync(FULLMASK, s2, off);
    }
    int w = t >> 5, lane = t & 31;
    if (lane == 0) { red1[w] = s1; red2[w] = s2; }
    __syncthreads();
    if (t == 0) {
        float a = 0.f, c = 0.f;
#pragma unroll
        for (int i = 0; i < 16; i++) { a += red1[i]; c += red2[i]; }
        float mu = a / (float)MH;
        float var = c / (float)MH - mu * mu;
        s_mu = mu;
        s_rstd = rsqrtf(var + 1e-5f);
    }
    __syncthreads();
    z[t] = (acc - s_mu) * s_rstd * lng[t] + lnb[t];
    __syncthreads();
    float o = mb2[t];
#pragma unroll 8
    for (int k = 0; k < MH; k++) o += z[k] * mW2[k * MO + t];
    out[(size_t)b * MO + t] = o;
}

// ---------------- launch ----------------
extern "C" void kernel_launch(void* const* d_in, const int* in_sizes, int n_in,
                              void* d_out, int out_size) {
    const float* x   = (const float*)d_in[0];
    const int*   ei  = (const int*)d_in[1];
    const int*   src = ei;
    const int*   dst = ei + E_EDGES;
    const float* ea  = (const float*)d_in[2];
    const int*   batch = (const int*)d_in[3];
    float* out = (float*)d_out;

    const float* Wl[3]  = { (const float*)d_in[4],  (const float*)d_in[11], (const float*)d_in[18] };
    const float* bl[3]  = { (const float*)d_in[5],  (const float*)d_in[12], (const float*)d_in[19] };
    const float* Wr[3]  = { (const float*)d_in[6],  (const float*)d_in[13], (const float*)d_in[20] };
    const float* br[3]  = { (const float*)d_in[7],  (const float*)d_in[14], (const float*)d_in[21] };
    const float* We[3]  = { (const float*)d_in[8],  (const float*)d_in[15], (const float*)d_in[22] };
    const float* att[3] = { (const float*)d_in[9],  (const float*)d_in[16], (const float*)d_in[23] };
    const float* bo[3]  = { (const float*)d_in[10], (const float*)d_in[17], (const float*)d_in[24] };
    const float* mW1 = (const float*)d_in[25];
    const float* mb1 = (const float*)d_in[26];
    const float* lng = (const float*)d_in[27];
    const float* lnb = (const float*)d_in[28];
    const float* mW2 = (const float*)d_in[29];
    const float* mb2 = (const float*)d_in[30];

    const int TB = 256;
    // preprocessing: CSR by dst + sorted edge attrs + self-loop attrs
    zero_prep_kernel<<<(N_NODES + TB - 1) / TB, TB>>>();
    hist_kernel<<<(E_EDGES + TB - 1) / TB, TB>>>(dst);
    scan1_kernel<<<SCAN_BLOCKS, 1024>>>();
    scan2_kernel<<<1, 64>>>();
    scan3_kernel<<<SCAN_BLOCKS, 1024>>>();
    scatter_kernel<<<(E_EDGES + TB - 1) / TB, TB>>>(src, dst, ea);
    loopattr_kernel<<<(N_NODES * 32 + TB - 1) / TB, TB>>>();

    const int lin_blocks = (N_NODES + 7) / 8;
    const int node_warp_blocks = (N_NODES * 32 + TB - 1) / TB;

    // layer 0: x -> g_h1
    lin_kernel<F_IN><<<lin_blocks, 128>>>(0, x, Wl[0], bl[0], Wr[0], br[0]);
    fused_gat_kernel<<<node_warp_blocks, TB>>>(We[0], att[0], bo[0], /*outsel=*/1, /*relu=*/1);
    // layer 1: g_h1 -> g_h2
    lin_kernel<HID><<<lin_blocks, 128>>>(1, x, Wl[1], bl[1], Wr[1], br[1]);
    fused_gat_kernel<<<node_warp_blocks, TB>>>(We[1], att[1], bo[1], /*outsel=*/2, /*relu=*/1);
    // layer 2: g_h2 -> g_h1
    lin_kernel<HID><<<lin_blocks, 128>>>(2, x, Wl[2], bl[2], Wr[2], br[2]);
    fused_gat_kernel<<<node_warp_blocks, TB>>>(We[2], att[2], bo[2], /*outsel=*/1, /*relu=*/0);

    // pooling + MLP head
    zero_pool_kernel<<<(G_GRAPHS * HID + TB - 1) / TB, TB>>>();
    pool_kernel<<<(N_NODES * HID + TB - 1) / TB, TB>>>(batch, /*insel=*/1);
    mlp_kernel<<<G_GRAPHS, MH>>>(mW1, mb1, lng, lnb, mW2, mb2, out);
}

// round 7
// speedup vs baseline: 1.4736x; 1.1911x over previous
#include <cuda_runtime.h>
#include <cstdint>

#define N_NODES 50000
#define E_EDGES 1600000
#define F_IN    32
#define HEADS   8
#define D_HEAD  16
#define HID     128
#define ED      16
#define G_GRAPHS 512
#define MH      512
#define MO      512
#define SLOPE   0.2f

#define FULLMASK 0xffffffffu

// ---------------- scratch (device globals; no allocation allowed) ----------------
__device__ int   g_deg[N_NODES];
__device__ int   g_cursor[N_NODES];
__device__ int   g_rowptr[N_NODES + 1];
__device__ int   g_bsum[64];
__device__ int   g_src_sorted[E_EDGES];
__device__ float g_ea_sorted[(size_t)E_EDGES * ED];
__device__ float g_loop_attr[(size_t)N_NODES * ED];
__device__ float g_xl[(size_t)N_NODES * HID];
__device__ float g_xr[(size_t)N_NODES * HID];
__device__ float g_h1[(size_t)N_NODES * HID];
__device__ float g_h2[(size_t)N_NODES * HID];
__device__ float g_pool[(size_t)G_GRAPHS * HID];

// ---------------- preprocessing ----------------
__global__ void zero_prep_kernel() {
    int i = blockIdx.x * blockDim.x + threadIdx.x;
    if (i < N_NODES) { g_deg[i] = 0; g_cursor[i] = 0; }
}

__global__ void zero_pool_kernel() {
    int i = blockIdx.x * blockDim.x + threadIdx.x;
    if (i < G_GRAPHS * HID) g_pool[i] = 0.f;
}

__global__ void hist_kernel(const int* __restrict__ dst) {
    int e = blockIdx.x * blockDim.x + threadIdx.x;
    if (e < E_EDGES) atomicAdd(&g_deg[dst[e]], 1);
}

// ---- 3-phase scan ----
#define SCAN_BLOCKS ((N_NODES + 1023) / 1024)

__global__ __launch_bounds__(1024) void scan1_kernel() {
    __shared__ int tmp[1024];
    int tid = threadIdx.x;
    int i = blockIdx.x * 1024 + tid;
    int v = (i < N_NODES) ? g_deg[i] : 0;
    tmp[tid] = v;
    __syncthreads();
#pragma unroll
    for (int off = 1; off < 1024; off <<= 1) {
        int t = (tid >= off) ? tmp[tid - off] : 0;
        __syncthreads();
        tmp[tid] += t;
        __syncthreads();
    }
    if (i < N_NODES) g_rowptr[i] = tmp[tid] - v;
    if (tid == 1023) g_bsum[blockIdx.x] = tmp[1023];
}

__global__ __launch_bounds__(64) void scan2_kernel() {
    __shared__ int tmp[64];
    int t = threadIdx.x;
    int v = (t < SCAN_BLOCKS) ? g_bsum[t] : 0;
    tmp[t] = v;
    __syncthreads();
#pragma unroll
    for (int off = 1; off < 64; off <<= 1) {
        int a = (t >= off) ? tmp[t - off] : 0;
        __syncthreads();
        tmp[t] += a;
        __syncthreads();
    }
    if (t < SCAN_BLOCKS) g_bsum[t] = tmp[t] - v;
    if (t == 0) g_rowptr[N_NODES] = E_EDGES;
}

__global__ __launch_bounds__(1024) void scan3_kernel() {
    int i = blockIdx.x * 1024 + threadIdx.x;
    if (i < N_NODES) g_rowptr[i] += g_bsum[blockIdx.x];
}

__global__ __launch_bounds__(256) void scatter_kernel(const int* __restrict__ src,
                                                      const int* __restrict__ dst,
                                                      const float* __restrict__ ea) {
    int e = blockIdx.x * blockDim.x + threadIdx.x;
    if (e >= E_EDGES) return;
    int d = dst[e];
    int slot = g_rowptr[d] + atomicAdd(&g_cursor[d], 1);
    g_src_sorted[slot] = src[e];
    const float4* s4 = (const float4*)(ea + (size_t)e * ED);
    float4* d4 = (float4*)(g_ea_sorted + (size_t)slot * ED);
    d4[0] = s4[0]; d4[1] = s4[1]; d4[2] = s4[2]; d4[3] = s4[3];
}

// warp per node: self-loop attr = mean of incoming edge_attr
__global__ __launch_bounds__(256) void loopattr_kernel() {
    int w = (blockIdx.x * blockDim.x + threadIdx.x) >> 5;
    int lane = threadIdx.x & 31;
    if (w >= N_NODES) return;
    int beg = g_rowptr[w], end = g_rowptr[w + 1];
    int cnt = end - beg;
    float inv = 1.f / (float)max(cnt, 1);
    if (lane < ED) {
        float s = 0.f;
        for (int p = beg; p < end; p++) s += g_ea_sorted[(size_t)p * ED + lane];
        g_loop_attr[(size_t)w * ED + lane] = s * inv;
    }
}

// ---------------- node linear transforms, 16 nodes/block ----------------
#define LIN_NPB 16
template<int F>
__global__ __launch_bounds__(128) void lin_kernel(int sel, const float* __restrict__ x,
                           const float* __restrict__ Wl, const float* __restrict__ bl,
                           const float* __restrict__ Wr, const float* __restrict__ br) {
    const float* hin = (sel == 0) ? x : (sel == 1 ? g_h1 : g_h2);
    __shared__ float hr[LIN_NPB][F];
    int v0 = blockIdx.x * LIN_NPB;
    int t = threadIdx.x;  // t = output column
    for (int i = t; i < LIN_NPB * F; i += 128) {
        int n = i / F, k = i - n * F;
        int v = v0 + n;
        hr[n][k] = (v < N_NODES) ? hin[(size_t)v * F + k] : 0.f;
    }
    __syncthreads();
    float bL = bl[t], bR = br[t];
    float al[LIN_NPB], ar[LIN_NPB];
#pragma unroll
    for (int n = 0; n < LIN_NPB; n++) { al[n] = bL; ar[n] = bR; }
#pragma unroll 2
    for (int k = 0; k < F; k++) {
        float wl = Wl[k * HID + t];
        float wr = Wr[k * HID + t];
#pragma unroll
        for (int n = 0; n < LIN_NPB; n++) {
            al[n] += hr[n][k] * wl;
            ar[n] += hr[n][k] * wr;
        }
    }
#pragma unroll
    for (int n = 0; n < LIN_NPB; n++) {
        int v = v0 + n;
        if (v < N_NODES) {
            g_xl[(size_t)v * HID + t] = al[n];
            g_xr[(size_t)v * HID + t] = ar[n];
        }
    }
}

// ---------------- fused scores + online-softmax + aggregation (warp per node) ----------------
// Lane owns 4 consecutive cols [4*lane, 4*lane+3] (one head per lane group of 4).
// 2 edges in flight per iteration; branchless online-softmax update.
__device__ __forceinline__ void online_update(float p, const float4& xls,
                                              float& mx, float& den, float4& acc) {
    float nmx = fmaxf(mx, p);
    float sc = __expf(mx - nmx);
    float f  = __expf(p - nmx);
    den = den * sc + f;
    acc.x = acc.x * sc + f * xls.x;
    acc.y = acc.y * sc + f * xls.y;
    acc.z = acc.z * sc + f * xls.z;
    acc.w = acc.w * sc + f * xls.w;
    mx = nmx;
}

__global__ __launch_bounds__(256, 2) void fused_gat_kernel(
    const float* __restrict__ We, const float* __restrict__ att,
    const float* __restrict__ bias, int outsel, int do_relu) {
    int v = (blockIdx.x * blockDim.x + threadIdx.x) >> 5;
    int lane = threadIdx.x & 31;
    if (v >= N_NODES) return;
    float* hout = (outsel == 1) ? g_h1 : g_h2;

    float4 w[ED];
#pragma unroll
    for (int k = 0; k < ED; k++) w[k] = ((const float4*)We)[k * 32 + lane];
    float4 att4 = ((const float4*)att)[lane];
    float4 xr4 = ((const float4*)g_xr)[(size_t)v * 32 + lane];

    int beg = g_rowptr[v], end = g_rowptr[v + 1];

    // ---- self-loop (initializes softmax state) ----
    float mx, den;
    float4 acc;
    {
        float eav = (lane < ED) ? g_loop_attr[(size_t)v * ED + lane] : 0.f;
        float4 xls = ((const float4*)g_xl)[(size_t)v * 32 + lane];
        float4 ee = make_float4(0.f, 0.f, 0.f, 0.f);
#pragma unroll
        for (int k = 0; k < ED; k++) {
            float a = __shfl_sync(FULLMASK, eav, k);
            ee.x += a * w[k].x; ee.y += a * w[k].y; ee.z += a * w[k].z; ee.w += a * w[k].w;
        }
        float m0 = xls.x + xr4.x + ee.x; m0 = fmaxf(m0, SLOPE * m0);
        float m1 = xls.y + xr4.y + ee.y; m1 = fmaxf(m1, SLOPE * m1);
        float m2 = xls.z + xr4.z + ee.z; m2 = fmaxf(m2, SLOPE * m2);
        float m3 = xls.w + xr4.w + ee.w; m3 = fmaxf(m3, SLOPE * m3);
        float p = m0 * att4.x + m1 * att4.y + m2 * att4.z + m3 * att4.w;
        p += __shfl_xor_sync(FULLMASK, p, 1);
        p += __shfl_xor_sync(FULLMASK, p, 2);
        mx = p; den = 1.f; acc = xls;
    }

    // ---- incoming edges, 2 at a time ----
    int e = beg;
    for (; e + 1 < end; e += 2) {
        int s0 = g_src_sorted[e];
        int s1 = g_src_sorted[e + 1];
        float ea0 = (lane < ED) ? g_ea_sorted[(size_t)e * ED + lane] : 0.f;
        float ea1 = (lane < ED) ? g_ea_sorted[(size_t)(e + 1) * ED + lane] : 0.f;
        float4 x0 = ((const float4*)g_xl)[(size_t)s0 * 32 + lane];
        float4 x1 = ((const float4*)g_xl)[(size_t)s1 * 32 + lane];
        float4 ee0 = make_float4(0.f, 0.f, 0.f, 0.f);
        float4 ee1 = make_float4(0.f, 0.f, 0.f, 0.f);
#pragma unroll
        for (int k = 0; k < ED; k++) {
            float a0 = __shfl_sync(FULLMASK, ea0, k);
            float a1 = __shfl_sync(FULLMASK, ea1, k);
            ee0.x += a0 * w[k].x; ee0.y += a0 * w[k].y; ee0.z += a0 * w[k].z; ee0.w += a0 * w[k].w;
            ee1.x += a1 * w[k].x; ee1.y += a1 * w[k].y; ee1.z += a1 * w[k].z; ee1.w += a1 * w[k].w;
        }
        float m0, m1, m2, m3;
        m0 = x0.x + xr4.x + ee0.x; m0 = fmaxf(m0, SLOPE * m0);
        m1 = x0.y + xr4.y + ee0.y; m1 = fmaxf(m1, SLOPE * m1);
        m2 = x0.z + xr4.z + ee0.z; m2 = fmaxf(m2, SLOPE * m2);
        m3 = x0.w + xr4.w + ee0.w; m3 = fmaxf(m3, SLOPE * m3);
        float p0 = m0 * att4.x + m1 * att4.y + m2 * att4.z + m3 * att4.w;
        m0 = x1.x + xr4.x + ee1.x; m0 = fmaxf(m0, SLOPE * m0);
        m1 = x1.y + xr4.y + ee1.y; m1 = fmaxf(m1, SLOPE * m1);
        m2 = x1.z + xr4.z + ee1.z; m2 = fmaxf(m2, SLOPE * m2);
        m3 = x1.w + xr4.w + ee1.w; m3 = fmaxf(m3, SLOPE * m3);
        float p1 = m0 * att4.x + m1 * att4.y + m2 * att4.z + m3 * att4.w;
        p0 += __shfl_xor_sync(FULLMASK, p0, 1);
        p1 += __shfl_xor_sync(FULLMASK, p1, 1);
        p0 += __shfl_xor_sync(FULLMASK, p0, 2);
        p1 += __shfl_xor_sync(FULLMASK, p1, 2);
        online_update(p0, x0, mx, den, acc);
        online_update(p1, x1, mx, den, acc);
    }
    if (e < end) {
        int s0 = g_src_sorted[e];
        float ea0 = (lane < ED) ? g_ea_sorted[(size_t)e * ED + lane] : 0.f;
        float4 x0 = ((const float4*)g_xl)[(size_t)s0 * 32 + lane];
        float4 ee0 = make_float4(0.f, 0.f, 0.f, 0.f);
#pragma unroll
        for (int k = 0; k < ED; k++) {
            float a0 = __shfl_sync(FULLMASK, ea0, k);
            ee0.x += a0 * w[k].x; ee0.y += a0 * w[k].y; ee0.z += a0 * w[k].z; ee0.w += a0 * w[k].w;
        }
        float m0 = x0.x + xr4.x + ee0.x; m0 = fmaxf(m0, SLOPE * m0);
        float m1 = x0.y + xr4.y + ee0.y; m1 = fmaxf(m1, SLOPE * m1);
        float m2 = x0.z + xr4.z + ee0.z; m2 = fmaxf(m2, SLOPE * m2);
        float m3 = x0.w + xr4.w + ee0.w; m3 = fmaxf(m3, SLOPE * m3);
        float p0 = m0 * att4.x + m1 * att4.y + m2 * att4.z + m3 * att4.w;
        p0 += __shfl_xor_sync(FULLMASK, p0, 1);
        p0 += __shfl_xor_sync(FULLMASK, p0, 2);
        online_update(p0, x0, mx, den, acc);
    }

    float inv = 1.f / den;
    float4 b4 = ((const float4*)bias)[lane];
    float4 o;
    o.x = acc.x * inv + b4.x; o.y = acc.y * inv + b4.y;
    o.z = acc.z * inv + b4.z; o.w = acc.w * inv + b4.w;
    if (do_relu) {
        o.x = fmaxf(o.x, 0.f); o.y = fmaxf(o.y, 0.f);
        o.z = fmaxf(o.z, 0.f); o.w = fmaxf(o.w, 0.f);
    }
    ((float4*)hout)[(size_t)v * 32 + lane] = o;
}

// ---------------- pooling ----------------
__global__ __launch_bounds__(256) void pool_kernel(const int* __restrict__ batch, int insel) {
    const float* hin = (insel == 1) ? g_h1 : g_h2;
    int idx = blockIdx.x * blockDim.x + threadIdx.x;
    if (idx >= N_NODES * HID) return;
    int v = idx >> 7;
    int c = idx & 127;
    atomicAdd(&g_pool[(size_t)batch[v] * HID + c], hin[idx]);
}

// ---------------- MLP head, 4 graphs/block ----------------
#define MLP_GPB 4
__global__ __launch_bounds__(512) void mlp_kernel(const float* __restrict__ mW1, const float* __restrict__ mb1,
                           const float* __restrict__ lng, const float* __restrict__ lnb,
                           const float* __restrict__ mW2, const float* __restrict__ mb2,
                           float* __restrict__ out) {
    int b0 = blockIdx.x * MLP_GPB;
    int t = threadIdx.x;  // 512 threads
    __shared__ float gr[MLP_GPB][HID];
    __shared__ float z[MLP_GPB][MH];
    __shared__ float red1[MLP_GPB][16], red2[MLP_GPB][16];
    __shared__ float s_mu[MLP_GPB], s_rstd[MLP_GPB];
    for (int i = t; i < MLP_GPB * HID; i += 512)
        gr[i / HID][i % HID] = g_pool[(size_t)(b0 + i / HID) * HID + (i % HID)];
    __syncthreads();
    float acc[MLP_GPB];
    float b1v = mb1[t];
#pragma unroll
    for (int g = 0; g < MLP_GPB; g++) acc[g] = b1v;
#pragma unroll 4
    for (int k = 0; k < HID; k++) {
        float w1 = mW1[k * MH + t];
#pragma unroll
        for (int g = 0; g < MLP_GPB; g++) acc[g] += gr[g][k] * w1;
    }
    float s1[MLP_GPB], s2[MLP_GPB];
#pragma unroll
    for (int g = 0; g < MLP_GPB; g++) {
        acc[g] = fmaxf(acc[g], 0.f);
        s1[g] = acc[g];
        s2[g] = acc[g] * acc[g];
    }
#pragma unroll
    for (int off = 16; off; off >>= 1) {
#pragma unroll
        for (int g = 0; g < MLP_GPB; g++) {
            s1[g] += __shfl_xor_sync(FULLMASK, s1[g], off);
            s2[g] += __shfl_xor_sync(FULLMASK, s2[g], off);
        }
    }
    int w = t >> 5, lane = t & 31;
    if (lane == 0) {
#pragma unroll
        for (int g = 0; g < MLP_GPB; g++) { red1[g][w] = s1[g]; red2[g][w] = s2[g]; }
    }
    __syncthreads();
    if (t < MLP_GPB) {
        float a = 0.f, c = 0.f;
#pragma unroll
        for (int i = 0; i < 16; i++) { a += red1[t][i]; c += red2[t][i]; }
        float mu = a / (float)MH;
        float var = c / (float)MH - mu * mu;
        s_mu[t] = mu;
        s_rstd[t] = rsqrtf(var + 1e-5f);
    }
    __syncthreads();
    float lg = lng[t], lb = lnb[t];
#pragma unroll
    for (int g = 0; g < MLP_GPB; g++)
        z[g][t] = (acc[g] - s_mu[g]) * s_rstd[g] * lg + lb;
    __syncthreads();
    float o[MLP_GPB];
    float b2v = mb2[t];
#pragma unroll
    for (int g = 0; g < MLP_GPB; g++) o[g] = b2v;
#pragma unroll 4
    for (int k = 0; k < MH; k++) {
        float w2 = mW2[k * MO + t];
#pragma unroll
        for (int g = 0; g < MLP_GPB; g++) o[g] += z[g][k] * w2;
    }
#pragma unroll
    for (int g = 0; g < MLP_GPB; g++)
        out[(size_t)(b0 + g) * MO + t] = o[g];
}

// ---------------- launch ----------------
extern "C" void kernel_launch(void* const* d_in, const int* in_sizes, int n_in,
                              void* d_out, int out_size) {
    const float* x   = (const float*)d_in[0];
    const int*   ei  = (const int*)d_in[1];
    const int*   src = ei;
    const int*   dst = ei + E_EDGES;
    const float* ea  = (const float*)d_in[2];
    const int*   batch = (const int*)d_in[3];
    float* out = (float*)d_out;

    const float* Wl[3]  = { (const float*)d_in[4],  (const float*)d_in[11], (const float*)d_in[18] };
    const float* bl[3]  = { (const float*)d_in[5],  (const float*)d_in[12], (const float*)d_in[19] };
    const float* Wr[3]  = { (const float*)d_in[6],  (const float*)d_in[13], (const float*)d_in[20] };
    const float* br[3]  = { (const float*)d_in[7],  (const float*)d_in[14], (const float*)d_in[21] };
    const float* We[3]  = { (const float*)d_in[8],  (const float*)d_in[15], (const float*)d_in[22] };
    const float* att[3] = { (const float*)d_in[9],  (const float*)d_in[16], (const float*)d_in[23] };
    const float* bo[3]  = { (const float*)d_in[10], (const float*)d_in[17], (const float*)d_in[24] };
    const float* mW1 = (const float*)d_in[25];
    const float* mb1 = (const float*)d_in[26];
    const float* lng = (const float*)d_in[27];
    const float* lnb = (const float*)d_in[28];
    const float* mW2 = (const float*)d_in[29];
    const float* mb2 = (const float*)d_in[30];

    const int TB = 256;
    zero_prep_kernel<<<(N_NODES + TB - 1) / TB, TB>>>();
    hist_kernel<<<(E_EDGES + TB - 1) / TB, TB>>>(dst);
    scan1_kernel<<<SCAN_BLOCKS, 1024>>>();
    scan2_kernel<<<1, 64>>>();
    scan3_kernel<<<SCAN_BLOCKS, 1024>>>();
    scatter_kernel<<<(E_EDGES + TB - 1) / TB, TB>>>(src, dst, ea);
    loopattr_kernel<<<(N_NODES * 32 + TB - 1) / TB, TB>>>();

    const int lin_blocks = (N_NODES + LIN_NPB - 1) / LIN_NPB;
    const int node_warp_blocks = (N_NODES * 32 + TB - 1) / TB;

    // layer 0: x -> g_h1
    lin_kernel<F_IN><<<lin_blocks, 128>>>(0, x, Wl[0], bl[0], Wr[0], br[0]);
    fused_gat_kernel<<<node_warp_blocks, TB>>>(We[0], att[0], bo[0], /*outsel=*/1, /*relu=*/1);
    // layer 1: g_h1 -> g_h2
    lin_kernel<HID><<<lin_blocks, 128>>>(1, x, Wl[1], bl[1], Wr[1], br[1]);
    fused_gat_kernel<<<node_warp_blocks, TB>>>(We[1], att[1], bo[1], /*outsel=*/2, /*relu=*/1);
    // layer 2: g_h2 -> g_h1
    lin_kernel<HID><<<lin_blocks, 128>>>(2, x, Wl[2], bl[2], Wr[2], br[2]);
    fused_gat_kernel<<<node_warp_blocks, TB>>>(We[2], att[2], bo[2], /*outsel=*/1, /*relu=*/0);

    // pooling + MLP head
    zero_pool_kernel<<<(G_GRAPHS * HID + TB - 1) / TB, TB>>>();
    pool_kernel<<<(N_NODES * HID + TB - 1) / TB, TB>>>(batch, /*insel=*/1);
    mlp_kernel<<<G_GRAPHS / MLP_GPB, MH>>>(mW1, mb1, lng, lnb, mW2, mb2, out);
}